// round 3
// baseline (speedup 1.0000x reference)
#include <cuda_runtime.h>
#include <math.h>

#define Nn 64
#define Hh 1024
#define FH 4096
#define Tt 512
#define Dd 1024

// Scratch (static device globals — no runtime allocation allowed)
__device__ float g_xw[(size_t)Tt * Nn * FH];   // (T, N, 4H) = 512 MB
__device__ float g_h[2][Nn * Hh];              // ping-pong hidden state
__device__ float g_c[Nn * Hh];                 // cell state

// ---------------------------------------------------------------------------
// init: h_buf[0] = h0, c = 0
// ---------------------------------------------------------------------------
__global__ void init_kernel(const float* __restrict__ h0) {
    int idx = blockIdx.x * blockDim.x + threadIdx.x;
    if (idx < Nn * Hh) {
        g_h[0][idx] = h0[idx];
        g_c[idx] = 0.0f;
    }
}

// ---------------------------------------------------------------------------
// Phase 1: g_xw[r][c] = sum_d x[n,t,d] * Wx[d,c] + b[c],  r = t*64 + n
// 128x128x8 tile, 256 threads, 8x8 register tile per thread.
// ---------------------------------------------------------------------------
__global__ __launch_bounds__(256, 2) void xw_gemm(const float* __restrict__ x,
                                                  const float* __restrict__ Wx,
                                                  const float* __restrict__ b) {
    __shared__ float As[8][132];   // transposed A tile: As[k][m]
    __shared__ float Bs[8][128];   // Bs[k][n]

    const int tid = threadIdx.x;
    const int tx = tid & 15;       // 16 col-groups
    const int ty = tid >> 4;       // 16 row-groups
    const int rBase = blockIdx.y * 128;
    const int cBase = blockIdx.x * 128;

    float acc[8][8];
#pragma unroll
    for (int i = 0; i < 8; i++)
#pragma unroll
        for (int j = 0; j < 8; j++) acc[i][j] = 0.0f;

    // A-load mapping: each thread loads one float4 of x
    const int row128 = tid >> 1;        // 0..127
    const int part = tid & 1;           // which half of the 8-wide k slab
    const int r = rBase + row128;
    const int an = r & 63;              // n
    const int at = r >> 6;              // t
    const float* aptr = x + ((size_t)an * Tt * Dd + (size_t)at * Dd + part * 4);

    // B-load mapping
    const int bkk = tid >> 5;           // 0..7
    const int bc4 = (tid & 31) * 4;     // 0..124
    const float* bptr = Wx + ((size_t)bkk * FH + cBase + bc4);

    for (int k0 = 0; k0 < Dd; k0 += 8) {
        float4 av = *(const float4*)(aptr + k0);
        float4 bv = *(const float4*)(bptr + (size_t)k0 * FH);
        As[part * 4 + 0][row128] = av.x;
        As[part * 4 + 1][row128] = av.y;
        As[part * 4 + 2][row128] = av.z;
        As[part * 4 + 3][row128] = av.w;
        *(float4*)&Bs[bkk][bc4] = bv;
        __syncthreads();

#pragma unroll
        for (int kk = 0; kk < 8; kk++) {
            float4 a0 = *(const float4*)&As[kk][ty * 8];
            float4 a1 = *(const float4*)&As[kk][ty * 8 + 4];
            float4 b0 = *(const float4*)&Bs[kk][tx * 8];
            float4 b1 = *(const float4*)&Bs[kk][tx * 8 + 4];
            float ar[8] = {a0.x, a0.y, a0.z, a0.w, a1.x, a1.y, a1.z, a1.w};
            float br[8] = {b0.x, b0.y, b0.z, b0.w, b1.x, b1.y, b1.z, b1.w};
#pragma unroll
            for (int i = 0; i < 8; i++)
#pragma unroll
                for (int j = 0; j < 8; j++) acc[i][j] += ar[i] * br[j];
        }
        __syncthreads();
    }

    // epilogue: add bias, store to g_xw
    float4 bb0 = *(const float4*)&b[cBase + tx * 8];
    float4 bb1 = *(const float4*)&b[cBase + tx * 8 + 4];
#pragma unroll
    for (int i = 0; i < 8; i++) {
        size_t row = (size_t)(rBase + ty * 8 + i);
        float4 o0 = make_float4(acc[i][0] + bb0.x, acc[i][1] + bb0.y,
                                acc[i][2] + bb0.z, acc[i][3] + bb0.w);
        float4 o1 = make_float4(acc[i][4] + bb1.x, acc[i][5] + bb1.y,
                                acc[i][6] + bb1.z, acc[i][7] + bb1.w);
        *(float4*)&g_xw[row * FH + cBase + tx * 8] = o0;
        *(float4*)&g_xw[row * FH + cBase + tx * 8 + 4] = o1;
    }
}

// ---------------------------------------------------------------------------
// Phase 2: one fused LSTM step.
// 128 CTAs; CTA owns h-columns [j0, j0+8) and computes the 4 gate strips
// (cols g*H + j0 + jj), i.e. a 64x32 tile of a = xw_t + h_prev @ Wh,
// then gates + c/h update in-CTA.
// Inner loop: LDS.128 (4 rows of h, transposed tile) + LDS.64 (2 w cols)
// per 8 FMAs, broadcast across the half-warp -> FMA-bound.
// ---------------------------------------------------------------------------
__global__ __launch_bounds__(256) void lstm_step(const float* __restrict__ Wh,
                                                 float* __restrict__ out,
                                                 int t) {
    __shared__ float hsT[32][68];  // hsT[kk][n], padded (68*4 % 16 == 0)
    __shared__ float ws[32][36];   // ws[kk][cc], padded

    const int tid = threadIdx.x;
    const int cp = tid & 15;   // column pair: cols 2cp, 2cp+1  (cc in [0,32))
    const int rg = tid >> 4;   // row group: rows rg*4 .. rg*4+3
    const int j0 = blockIdx.x * 8;

    const float* __restrict__ hprev = g_h[t & 1];
    float* __restrict__ hnext = g_h[(t + 1) & 1];
    const float* __restrict__ xwt = g_xw + (size_t)t * Nn * FH;

    float acc[4][2];
#pragma unroll
    for (int i = 0; i < 4; i++)
#pragma unroll
        for (int j = 0; j < 2; j++) {
            int cc = 2 * cp + j;
            int gcol = (cc >> 3) * Hh + j0 + (cc & 7);
            acc[i][j] = xwt[(size_t)(rg * 4 + i) * FH + gcol];
        }

    // per-tile load indices
    const int wkk = tid >> 3;          // 0..31
    const int wseg = tid & 7;          // 0..7
    const int wg = wseg >> 1;          // gate block 0..3
    const int whalf = wseg & 1;        // float4 half of 8-wide strip

    for (int k0 = 0; k0 < Hh; k0 += 32) {
        // load h tile transposed: hsT[kk][n]
#pragma unroll
        for (int q = 0; q < 2; q++) {
            int l = tid + 256 * q;       // 0..511
            int n = l >> 3;              // 0..63
            int k4 = l & 7;              // which float4 in the 32-wide k slab
            float4 v = *(const float4*)&hprev[n * Hh + k0 + k4 * 4];
            hsT[k4 * 4 + 0][n] = v.x;
            hsT[k4 * 4 + 1][n] = v.y;
            hsT[k4 * 4 + 2][n] = v.z;
            hsT[k4 * 4 + 3][n] = v.w;
        }
        // load Wh tile: ws[kk][cc], cc = g*8 + jj
        {
            float4 w = *(const float4*)&Wh[(size_t)(k0 + wkk) * FH + wg * Hh + j0 + whalf * 4];
            *(float4*)&ws[wkk][wseg * 4] = w;
        }
        __syncthreads();

#pragma unroll
        for (int kk = 0; kk < 32; kk++) {
            float4 hv = *(const float4*)&hsT[kk][rg * 4];
            float2 wv = *(const float2*)&ws[kk][2 * cp];
            acc[0][0] += hv.x * wv.x;  acc[0][1] += hv.x * wv.y;
            acc[1][0] += hv.y * wv.x;  acc[1][1] += hv.y * wv.y;
            acc[2][0] += hv.z * wv.x;  acc[2][1] += hv.z * wv.y;
            acc[3][0] += hv.w * wv.x;  acc[3][1] += hv.w * wv.y;
        }
        __syncthreads();
    }

    // exchange: a-tile to smem (alias hsT: 2176 floats >= 64*33 = 2112)
    float* sa = &hsT[0][0];
#pragma unroll
    for (int i = 0; i < 4; i++)
#pragma unroll
        for (int j = 0; j < 2; j++)
            sa[(rg * 4 + i) * 33 + 2 * cp + j] = acc[i][j];
    __syncthreads();

    // gates + state update: 512 (n, jj) pairs, 2 per thread
#pragma unroll
    for (int q = 0; q < 2; q++) {
        int idx = tid + 256 * q;     // 0..511
        int n = idx >> 3;
        int jj = idx & 7;
        float ai = sa[n * 33 + jj];
        float af = sa[n * 33 + 8 + jj];
        float ao = sa[n * 33 + 16 + jj];
        float ag = sa[n * 33 + 24 + jj];
        float ig = 1.0f / (1.0f + expf(-ai));
        float fg = 1.0f / (1.0f + expf(-af));
        float og = 1.0f / (1.0f + expf(-ao));
        float gg = tanhf(ag);
        int col = j0 + jj;
        float c = fg * g_c[n * Hh + col] + ig * gg;
        float h = og * tanhf(c);
        g_c[n * Hh + col] = c;
        hnext[n * Hh + col] = h;
        out[(size_t)n * Tt * Hh + (size_t)t * Hh + col] = h;
    }
}

// ---------------------------------------------------------------------------
// launch
// ---------------------------------------------------------------------------
extern "C" void kernel_launch(void* const* d_in, const int* in_sizes, int n_in,
                              void* d_out, int out_size) {
    const float* x  = (const float*)d_in[0];   // (N, T, D)
    const float* h0 = (const float*)d_in[1];   // (N, H)
    const float* Wx = (const float*)d_in[2];   // (D, 4H)
    const float* Wh = (const float*)d_in[3];   // (H, 4H)
    const float* b  = (const float*)d_in[4];   // (4H,)
    float* out = (float*)d_out;                // (N, T, H)

    init_kernel<<<(Nn * Hh + 255) / 256, 256>>>(h0);

    dim3 g1(FH / 128, (Tt * Nn) / 128);        // (32, 256)
    xw_gemm<<<g1, 256>>>(x, Wx, b);

    for (int t = 0; t < Tt; t++) {
        lstm_step<<<128, 256>>>(Wh, out, t);
    }
}

// round 6
// speedup vs baseline: 1.2671x; 1.2671x over previous
#include <cuda_runtime.h>
#include <math.h>

#define Nn 64
#define Hh 1024
#define FH 4096
#define Tt 512
#define Dd 1024
#define NCTA 128

// Scratch (static device globals — no runtime allocation allowed)
__device__ float g_xw[(size_t)Tt * Nn * FH];   // (T, N, 4H) = 512 MB
__device__ float g_h[2][Nn * Hh];              // ping-pong hidden state
__device__ unsigned g_bar;                     // grid barrier counter

// ---------------------------------------------------------------------------
// init: h_buf[0] = h0, reset barrier
// ---------------------------------------------------------------------------
__global__ void init_kernel(const float* __restrict__ h0) {
    int idx = blockIdx.x * blockDim.x + threadIdx.x;
    if (idx < Nn * Hh) {
        g_h[0][idx] = h0[idx];
    }
    if (idx == 0) g_bar = 0;
}

// ---------------------------------------------------------------------------
// Phase 1: g_xw[r][c] = sum_d x[n,t,d] * Wx[d,c] + b[c],  r = t*64 + n
// 128x128x8 tile, 256 threads, 8x8 register tile per thread. (unchanged)
// ---------------------------------------------------------------------------
__global__ __launch_bounds__(256, 2) void xw_gemm(const float* __restrict__ x,
                                                  const float* __restrict__ Wx,
                                                  const float* __restrict__ b) {
    __shared__ float As[8][132];
    __shared__ float Bs[8][128];

    const int tid = threadIdx.x;
    const int tx = tid & 15;
    const int ty = tid >> 4;
    const int rBase = blockIdx.y * 128;
    const int cBase = blockIdx.x * 128;

    float acc[8][8];
#pragma unroll
    for (int i = 0; i < 8; i++)
#pragma unroll
        for (int j = 0; j < 8; j++) acc[i][j] = 0.0f;

    const int row128 = tid >> 1;
    const int part = tid & 1;
    const int r = rBase + row128;
    const int an = r & 63;
    const int at = r >> 6;
    const float* aptr = x + ((size_t)an * Tt * Dd + (size_t)at * Dd + part * 4);

    const int bkk = tid >> 5;
    const int bc4 = (tid & 31) * 4;
    const float* bptr = Wx + ((size_t)bkk * FH + cBase + bc4);

    for (int k0 = 0; k0 < Dd; k0 += 8) {
        float4 av = *(const float4*)(aptr + k0);
        float4 bv = *(const float4*)(bptr + (size_t)k0 * FH);
        As[part * 4 + 0][row128] = av.x;
        As[part * 4 + 1][row128] = av.y;
        As[part * 4 + 2][row128] = av.z;
        As[part * 4 + 3][row128] = av.w;
        *(float4*)&Bs[bkk][bc4] = bv;
        __syncthreads();

#pragma unroll
        for (int kk = 0; kk < 8; kk++) {
            float4 a0 = *(const float4*)&As[kk][ty * 8];
            float4 a1 = *(const float4*)&As[kk][ty * 8 + 4];
            float4 b0 = *(const float4*)&Bs[kk][tx * 8];
            float4 b1 = *(const float4*)&Bs[kk][tx * 8 + 4];
            float ar[8] = {a0.x, a0.y, a0.z, a0.w, a1.x, a1.y, a1.z, a1.w};
            float br[8] = {b0.x, b0.y, b0.z, b0.w, b1.x, b1.y, b1.z, b1.w};
#pragma unroll
            for (int i = 0; i < 8; i++)
#pragma unroll
                for (int j = 0; j < 8; j++) acc[i][j] += ar[i] * br[j];
        }
        __syncthreads();
    }

    float4 bb0 = *(const float4*)&b[cBase + tx * 8];
    float4 bb1 = *(const float4*)&b[cBase + tx * 8 + 4];
#pragma unroll
    for (int i = 0; i < 8; i++) {
        size_t row = (size_t)(rBase + ty * 8 + i);
        float4 o0 = make_float4(acc[i][0] + bb0.x, acc[i][1] + bb0.y,
                                acc[i][2] + bb0.z, acc[i][3] + bb0.w);
        float4 o1 = make_float4(acc[i][4] + bb1.x, acc[i][5] + bb1.y,
                                acc[i][6] + bb1.z, acc[i][7] + bb1.w);
        *(float4*)&g_xw[row * FH + cBase + tx * 8] = o0;
        *(float4*)&g_xw[row * FH + cBase + tx * 8 + 4] = o1;
    }
}

// ---------------------------------------------------------------------------
// Phase 2: persistent fused LSTM over all 512 steps.
// 128 CTAs (<= 148 SMs -> all co-resident, custom grid barrier is safe).
// CTA owns h-columns [j0, j0+8): keeps its Wh slice (1024x32) in smem for the
// whole kernel, keeps its c columns in registers, double-buffers h tiles.
// Dyn smem: ws 1024*32 + h double buffer 2*32*68  = 148480 B.
// ---------------------------------------------------------------------------
extern __shared__ float sdyn[];

__global__ __launch_bounds__(256) void lstm_persist(const float* __restrict__ Wh,
                                                    float* __restrict__ out) {
    float* ws = sdyn;                 // [1024][32]
    float* hb = sdyn + 32768;         // [2][32][68]

    const int tid = threadIdx.x;
    const int cp = tid & 15;          // column pair (cc = 2cp, 2cp+1)
    const int rg = tid >> 4;          // row group (rows rg*4..rg*4+3)
    const int j0 = blockIdx.x * 8;

    // ---- preload Wh slice into smem (once) ----
    for (int idx = tid; idx < 8192; idx += 256) {
        int k = idx >> 3, seg = idx & 7, g = seg >> 1, hf = seg & 1;
        float4 v = *(const float4*)&Wh[(size_t)k * FH + g * Hh + j0 + hf * 4];
        *(float4*)&ws[k * 32 + seg * 4] = v;
    }

    // epilogue-mapping constants (thread handles idx = tid, tid+256)
    const int en0 = tid >> 3, ej0 = tid & 7;
    const int en1 = (tid + 256) >> 3, ej1 = (tid + 256) & 7;
    float creg0 = 0.0f, creg1 = 0.0f;   // persistent cell state

    // h-tile load mapping (2 float4 per thread per tile)
    const int ln0 = tid >> 3, lk0 = tid & 7;
    const int ln1 = (tid + 256) >> 3, lk1 = (tid + 256) & 7;

    __syncthreads();

    for (int t = 0; t < Tt; t++) {
        const float* __restrict__ hprev = g_h[t & 1];
        float* __restrict__ hnext = g_h[(t + 1) & 1];
        const float* __restrict__ xwt = g_xw + (size_t)t * Nn * FH;

        // init acc from xw slab
        float acc[4][2];
#pragma unroll
        for (int i = 0; i < 4; i++)
#pragma unroll
            for (int j = 0; j < 2; j++) {
                int cc = 2 * cp + j;
                int gcol = (cc >> 3) * Hh + j0 + (cc & 7);
                acc[i][j] = __ldg(&xwt[(size_t)(rg * 4 + i) * FH + gcol]);
            }

        // preload h tile 0
        float4 p0 = __ldcg((const float4*)&hprev[ln0 * Hh + lk0 * 4]);
        float4 p1 = __ldcg((const float4*)&hprev[ln1 * Hh + lk1 * 4]);
        {
            float* b0 = hb;  // buffer 0
            b0[(lk0 * 4 + 0) * 68 + ln0] = p0.x;
            b0[(lk0 * 4 + 1) * 68 + ln0] = p0.y;
            b0[(lk0 * 4 + 2) * 68 + ln0] = p0.z;
            b0[(lk0 * 4 + 3) * 68 + ln0] = p0.w;
            b0[(lk1 * 4 + 0) * 68 + ln1] = p1.x;
            b0[(lk1 * 4 + 1) * 68 + ln1] = p1.y;
            b0[(lk1 * 4 + 2) * 68 + ln1] = p1.z;
            b0[(lk1 * 4 + 3) * 68 + ln1] = p1.w;
        }
        __syncthreads();

        for (int tile = 0; tile < 32; tile++) {
            const float* cur = hb + (tile & 1) * 2176;
            const float* wsp = ws + tile * 1024;   // tile*32 rows * 32 cols

            if (tile < 31) {
                int k0n = (tile + 1) * 32;
                p0 = __ldcg((const float4*)&hprev[ln0 * Hh + k0n + lk0 * 4]);
                p1 = __ldcg((const float4*)&hprev[ln1 * Hh + k0n + lk1 * 4]);
            }

#pragma unroll
            for (int kk = 0; kk < 32; kk++) {
                float4 hv = *(const float4*)&cur[kk * 68 + rg * 4];
                float2 wv = *(const float2*)&wsp[kk * 32 + 2 * cp];
                acc[0][0] += hv.x * wv.x;  acc[0][1] += hv.x * wv.y;
                acc[1][0] += hv.y * wv.x;  acc[1][1] += hv.y * wv.y;
                acc[2][0] += hv.z * wv.x;  acc[2][1] += hv.z * wv.y;
                acc[3][0] += hv.w * wv.x;  acc[3][1] += hv.w * wv.y;
            }

            if (tile < 31) {
                float* nxt = hb + ((tile + 1) & 1) * 2176;
                nxt[(lk0 * 4 + 0) * 68 + ln0] = p0.x;
                nxt[(lk0 * 4 + 1) * 68 + ln0] = p0.y;
                nxt[(lk0 * 4 + 2) * 68 + ln0] = p0.z;
                nxt[(lk0 * 4 + 3) * 68 + ln0] = p0.w;
                nxt[(lk1 * 4 + 0) * 68 + ln1] = p1.x;
                nxt[(lk1 * 4 + 1) * 68 + ln1] = p1.y;
                nxt[(lk1 * 4 + 2) * 68 + ln1] = p1.z;
                nxt[(lk1 * 4 + 3) * 68 + ln1] = p1.w;
                __syncthreads();
            }
        }

        // ---- gate exchange via smem (reuse hb; sync first: warps may still
        // be reading the last tile) ----
        __syncthreads();
        float* sa = hb;   // 64*33 = 2112 floats < 4352
#pragma unroll
        for (int i = 0; i < 4; i++)
#pragma unroll
            for (int j = 0; j < 2; j++)
                sa[(rg * 4 + i) * 33 + 2 * cp + j] = acc[i][j];
        __syncthreads();

        // gates + state update (2 (n,jj) pairs per thread, fixed mapping)
        {
            float ai = sa[en0 * 33 + ej0];
            float af = sa[en0 * 33 + 8 + ej0];
            float ao = sa[en0 * 33 + 16 + ej0];
            float ag = sa[en0 * 33 + 24 + ej0];
            float ig = 1.0f / (1.0f + expf(-ai));
            float fg = 1.0f / (1.0f + expf(-af));
            float og = 1.0f / (1.0f + expf(-ao));
            float gg = tanhf(ag);
            creg0 = fg * creg0 + ig * gg;
            float h = og * tanhf(creg0);
            int col = j0 + ej0;
            hnext[en0 * Hh + col] = h;
            out[(size_t)en0 * Tt * Hh + (size_t)t * Hh + col] = h;
        }
        {
            float ai = sa[en1 * 33 + ej1];
            float af = sa[en1 * 33 + 8 + ej1];
            float ao = sa[en1 * 33 + 16 + ej1];
            float ag = sa[en1 * 33 + 24 + ej1];
            float ig = 1.0f / (1.0f + expf(-ai));
            float fg = 1.0f / (1.0f + expf(-af));
            float og = 1.0f / (1.0f + expf(-ao));
            float gg = tanhf(ag);
            creg1 = fg * creg1 + ig * gg;
            float h = og * tanhf(creg1);
            int col = j0 + ej1;
            hnext[en1 * Hh + col] = h;
            out[(size_t)en1 * Tt * Hh + (size_t)t * Hh + col] = h;
        }

        // ---- grid barrier (release: fence+arrive, acquire: spin+fence) ----
        if (t < Tt - 1) {
            __threadfence();
            __syncthreads();
            if (tid == 0) {
                atomicAdd(&g_bar, 1u);
                unsigned target = (unsigned)NCTA * (unsigned)(t + 1);
                while (*(volatile unsigned*)&g_bar < target) { }
                __threadfence();
            }
            __syncthreads();
        }
    }
}

// ---------------------------------------------------------------------------
// launch
// ---------------------------------------------------------------------------
extern "C" void kernel_launch(void* const* d_in, const int* in_sizes, int n_in,
                              void* d_out, int out_size) {
    const float* x  = (const float*)d_in[0];   // (N, T, D)
    const float* h0 = (const float*)d_in[1];   // (N, H)
    const float* Wx = (const float*)d_in[2];   // (D, 4H)
    const float* Wh = (const float*)d_in[3];   // (H, 4H)
    const float* b  = (const float*)d_in[4];   // (4H,)
    float* out = (float*)d_out;                // (N, T, H)

    static int smem_set = 0;
    const int dyn_smem = (32768 + 2 * 32 * 68) * 4;   // 148480 B
    if (!smem_set) {
        cudaFuncSetAttribute(lstm_persist,
                             cudaFuncAttributeMaxDynamicSharedMemorySize,
                             dyn_smem);
        smem_set = 1;
    }

    init_kernel<<<(Nn * Hh + 255) / 256, 256>>>(h0);

    dim3 g1(FH / 128, (Tt * Nn) / 128);        // (32, 256)
    xw_gemm<<<g1, 256>>>(x, Wx, b);

    lstm_persist<<<NCTA, 256, dyn_smem>>>(Wh, out);
}

// round 9
// speedup vs baseline: 1.5172x; 1.1974x over previous
#include <cuda_runtime.h>
#include <cuda_bf16.h>
#include <math.h>
#include <cstdint>

#define Nn 64
#define Hh 1024
#define FH 4096
#define Tt 512
#define Dd 1024
#define NCTA 128
#define Rr (Tt * Nn)        // 32768 GEMM rows

// ---------------------------------------------------------------------------
// Scratch (static device globals — no runtime allocation allowed)
// ---------------------------------------------------------------------------
__device__ float g_xw[(size_t)Tt * Nn * FH];        // (T*N, 4H) fp32, 512 MB
__device__ float g_h[2][Nn * Hh];                   // ping-pong hidden state
__device__ unsigned g_bar;                          // grid barrier counter
__device__ __nv_bfloat16 g_xhi[(size_t)Rr * Dd];    // x split hi (row r = t*64+n)
__device__ __nv_bfloat16 g_xlo[(size_t)Rr * Dd];    // x split lo
__device__ __nv_bfloat16 g_wthi[(size_t)FH * Dd];   // Wx^T split hi  [c][k]
__device__ __nv_bfloat16 g_wtlo[(size_t)FH * Dd];   // Wx^T split lo

__device__ __forceinline__ uint32_t smem_u32(const void* p) {
    uint32_t a;
    asm("{ .reg .u64 t; cvta.to.shared.u64 t, %1; cvt.u32.u64 %0, t; }"
        : "=r"(a) : "l"(p));
    return a;
}

// ---------------------------------------------------------------------------
// init: h_buf[0] = h0, reset barrier
// ---------------------------------------------------------------------------
__global__ void init_kernel(const float* __restrict__ h0) {
    int idx = blockIdx.x * blockDim.x + threadIdx.x;
    if (idx < Nn * Hh) g_h[0][idx] = h0[idx];
    if (idx == 0) g_bar = 0;
}

// ---------------------------------------------------------------------------
// split x into bf16 hi/lo, reindexed to GEMM rows r = t*64 + n
// ---------------------------------------------------------------------------
__global__ void split_x(const float* __restrict__ x) {
    size_t q = (size_t)blockIdx.x * blockDim.x + threadIdx.x;  // quad index
    if (q >= (size_t)Rr * Dd / 4) return;
    size_t e = q * 4;
    int r = (int)(e >> 10);
    int k = (int)(e & 1023);
    int n = r & 63, t = r >> 6;
    float4 v = *(const float4*)&x[(size_t)n * Tt * Dd + (size_t)t * Dd + k];
    __nv_bfloat16 h[4], l[4];
    float vv[4] = {v.x, v.y, v.z, v.w};
#pragma unroll
    for (int i = 0; i < 4; i++) {
        h[i] = __float2bfloat16(vv[i]);
        l[i] = __float2bfloat16(vv[i] - __bfloat162float(h[i]));
    }
    *(uint2*)&g_xhi[e] = *(uint2*)h;
    *(uint2*)&g_xlo[e] = *(uint2*)l;
}

// ---------------------------------------------------------------------------
// split + transpose Wx into bf16 hi/lo:  g_wt*[c][k] = split(Wx[k][c])
// ---------------------------------------------------------------------------
__global__ void split_w(const float* __restrict__ Wx) {
    size_t q = (size_t)blockIdx.x * blockDim.x + threadIdx.x;
    if (q >= (size_t)FH * Dd / 4) return;
    size_t e = q * 4;
    int c = (int)(e >> 10);
    int k = (int)(e & 1023);
    __nv_bfloat16 h[4], l[4];
#pragma unroll
    for (int i = 0; i < 4; i++) {
        float v = Wx[(size_t)(k + i) * FH + c];
        h[i] = __float2bfloat16(v);
        l[i] = __float2bfloat16(v - __bfloat162float(h[i]));
    }
    *(uint2*)&g_wthi[e] = *(uint2*)h;
    *(uint2*)&g_wtlo[e] = *(uint2*)l;
}

// ---------------------------------------------------------------------------
// Phase 1 GEMM on HMMA (mma.sync bf16): g_xw = x @ Wx + b, 3-term split.
// CTA 128x128, 8 warps of 64x32, K chunks of 64 bf16, 48 chunks =
// 3 passes (hi*hi, hi*lo, lo*hi) x 16 chunks of the K=1024 reduction.
// smem rows padded to 72 bf16 (144 B): ldmatrix phases conflict-free.
// ---------------------------------------------------------------------------
#define LDA_S 72

__global__ __launch_bounds__(256, 1) void xw_tc(const float* __restrict__ b) {
    __shared__ alignas(16) __nv_bfloat16 sA[128 * LDA_S];   // [m][k]
    __shared__ alignas(16) __nv_bfloat16 sB[128 * LDA_S];   // [n][k]

    const int tid = threadIdx.x;
    const int wid = tid >> 5;
    const int lane = tid & 31;
    const int rBase = blockIdx.y * 128;
    const int cBase = blockIdx.x * 128;

    const int wm = (wid >> 2) * 64;   // warp m offset
    const int wn = (wid & 3) * 32;    // warp n offset

    const uint32_t saA = smem_u32(sA);
    const uint32_t saB = smem_u32(sB);

    // precomputed ldmatrix base addresses (bytes)
    // A: row = wm + i*16 + (lane&15), col = (lane>>4)*8
    const uint32_t aRow = wm + (lane & 15);
    const uint32_t aCol = (lane >> 4) * 8;
    // B: matrix j = lane>>3: row = wn + jp*16 + (j>>1)*8 + (lane&7), col = (j&1)*8
    const uint32_t bRow = wn + ((lane >> 4) & 1) * 8 + (lane & 7);
    const uint32_t bCol = ((lane >> 3) & 1) * 8;

    float acc[4][4][4];   // [mblk][nblk][frag]
#pragma unroll
    for (int i = 0; i < 4; i++)
#pragma unroll
        for (int j = 0; j < 4; j++)
#pragma unroll
            for (int f = 0; f < 4; f++) acc[i][j][f] = 0.0f;

    const __nv_bfloat16* Asrc[3] = {g_xhi, g_xhi, g_xlo};
    const __nv_bfloat16* Bsrc[3] = {g_wthi, g_wtlo, g_wthi};

    // global load mapping: 4 float4 (8 bf16) per operand per thread
    float4 ra[4], rb[4];
    const int row_[4] = {tid >> 3, (tid + 256) >> 3, (tid + 512) >> 3, (tid + 768) >> 3};
    const int seg_[4] = {tid & 7, (tid + 256) & 7, (tid + 512) & 7, (tid + 768) & 7};

#pragma unroll
    for (int qq = 0; qq < 4; qq++) {
        ra[qq] = *(const float4*)&Asrc[0][(size_t)(rBase + row_[qq]) * Dd + seg_[qq] * 8];
        rb[qq] = *(const float4*)&Bsrc[0][(size_t)(cBase + row_[qq]) * Dd + seg_[qq] * 8];
    }

    for (int c = 0; c < 48; c++) {
        // store prefetched chunk into smem
#pragma unroll
        for (int qq = 0; qq < 4; qq++) {
            *(float4*)&sA[row_[qq] * LDA_S + seg_[qq] * 8] = ra[qq];
            *(float4*)&sB[row_[qq] * LDA_S + seg_[qq] * 8] = rb[qq];
        }
        __syncthreads();

        // prefetch next chunk (overlaps with mma work below)
        if (c < 47) {
            int nc = c + 1;
            int p = nc >> 4;
            int kc = (nc & 15) * 64;
            const __nv_bfloat16* ap = Asrc[p];
            const __nv_bfloat16* bp = Bsrc[p];
#pragma unroll
            for (int qq = 0; qq < 4; qq++) {
                ra[qq] = *(const float4*)&ap[(size_t)(rBase + row_[qq]) * Dd + kc + seg_[qq] * 8];
                rb[qq] = *(const float4*)&bp[(size_t)(cBase + row_[qq]) * Dd + kc + seg_[qq] * 8];
            }
        }

#pragma unroll
        for (int ks = 0; ks < 4; ks++) {
            const uint32_t kb = ks * 16;
            uint32_t af[4][4];
            uint32_t bf[2][4];
#pragma unroll
            for (int i = 0; i < 4; i++) {
                uint32_t addr = saA + ((aRow + i * 16) * LDA_S + kb + aCol) * 2;
                asm volatile(
                    "ldmatrix.sync.aligned.m8n8.x4.shared.b16 {%0,%1,%2,%3}, [%4];"
                    : "=r"(af[i][0]), "=r"(af[i][1]), "=r"(af[i][2]), "=r"(af[i][3])
                    : "r"(addr));
            }
#pragma unroll
            for (int jp = 0; jp < 2; jp++) {
                uint32_t addr = saB + ((bRow + jp * 16) * LDA_S + kb + bCol) * 2;
                asm volatile(
                    "ldmatrix.sync.aligned.m8n8.x4.shared.b16 {%0,%1,%2,%3}, [%4];"
                    : "=r"(bf[jp][0]), "=r"(bf[jp][1]), "=r"(bf[jp][2]), "=r"(bf[jp][3])
                    : "r"(addr));
            }
#pragma unroll
            for (int i = 0; i < 4; i++)
#pragma unroll
                for (int j = 0; j < 4; j++) {
                    uint32_t b0 = bf[j >> 1][(j & 1) * 2 + 0];
                    uint32_t b1 = bf[j >> 1][(j & 1) * 2 + 1];
                    asm volatile(
                        "mma.sync.aligned.m16n8k16.row.col.f32.bf16.bf16.f32 "
                        "{%0,%1,%2,%3}, {%4,%5,%6,%7}, {%8,%9}, {%0,%1,%2,%3};"
                        : "+f"(acc[i][j][0]), "+f"(acc[i][j][1]),
                          "+f"(acc[i][j][2]), "+f"(acc[i][j][3])
                        : "r"(af[i][0]), "r"(af[i][1]), "r"(af[i][2]), "r"(af[i][3]),
                          "r"(b0), "r"(b1));
                }
        }
        __syncthreads();
    }

    // epilogue: add bias, store fp32 tile
    const int er = lane >> 2;          // 0..7
    const int ec = (lane & 3) * 2;     // 0,2,4,6
#pragma unroll
    for (int i = 0; i < 4; i++) {
        const size_t r0 = (size_t)(rBase + wm + i * 16 + er);
        const size_t r1 = r0 + 8;
#pragma unroll
        for (int j = 0; j < 4; j++) {
            const int cc = cBase + wn + j * 8 + ec;
            float2 bb = *(const float2*)&b[cc];
            float2 o0 = make_float2(acc[i][j][0] + bb.x, acc[i][j][1] + bb.y);
            float2 o1 = make_float2(acc[i][j][2] + bb.x, acc[i][j][3] + bb.y);
            *(float2*)&g_xw[r0 * FH + cc] = o0;
            *(float2*)&g_xw[r1 * FH + cc] = o1;
        }
    }
}

// ---------------------------------------------------------------------------
// Phase 2: persistent fused LSTM over all 512 steps (unchanged, known good).
// ---------------------------------------------------------------------------
extern __shared__ float sdyn[];

__global__ __launch_bounds__(256) void lstm_persist(const float* __restrict__ Wh,
                                                    float* __restrict__ out) {
    float* ws = sdyn;                 // [1024][32]
    float* hb = sdyn + 32768;         // [2][32][68]

    const int tid = threadIdx.x;
    const int cp = tid & 15;
    const int rg = tid >> 4;
    const int j0 = blockIdx.x * 8;

    for (int idx = tid; idx < 8192; idx += 256) {
        int k = idx >> 3, seg = idx & 7, g = seg >> 1, hf = seg & 1;
        float4 v = *(const float4*)&Wh[(size_t)k * FH + g * Hh + j0 + hf * 4];
        *(float4*)&ws[k * 32 + seg * 4] = v;
    }

    const int en0 = tid >> 3, ej0 = tid & 7;
    const int en1 = (tid + 256) >> 3, ej1 = (tid + 256) & 7;
    float creg0 = 0.0f, creg1 = 0.0f;

    const int ln0 = tid >> 3, lk0 = tid & 7;
    const int ln1 = (tid + 256) >> 3, lk1 = (tid + 256) & 7;

    __syncthreads();

    for (int t = 0; t < Tt; t++) {
        const float* __restrict__ hprev = g_h[t & 1];
        float* __restrict__ hnext = g_h[(t + 1) & 1];
        const float* __restrict__ xwt = g_xw + (size_t)t * Nn * FH;

        float acc[4][2];
#pragma unroll
        for (int i = 0; i < 4; i++)
#pragma unroll
            for (int j = 0; j < 2; j++) {
                int cc = 2 * cp + j;
                int gcol = (cc >> 3) * Hh + j0 + (cc & 7);
                acc[i][j] = __ldg(&xwt[(size_t)(rg * 4 + i) * FH + gcol]);
            }

        float4 p0 = __ldcg((const float4*)&hprev[ln0 * Hh + lk0 * 4]);
        float4 p1 = __ldcg((const float4*)&hprev[ln1 * Hh + lk1 * 4]);
        {
            float* b0 = hb;
            b0[(lk0 * 4 + 0) * 68 + ln0] = p0.x;
            b0[(lk0 * 4 + 1) * 68 + ln0] = p0.y;
            b0[(lk0 * 4 + 2) * 68 + ln0] = p0.z;
            b0[(lk0 * 4 + 3) * 68 + ln0] = p0.w;
            b0[(lk1 * 4 + 0) * 68 + ln1] = p1.x;
            b0[(lk1 * 4 + 1) * 68 + ln1] = p1.y;
            b0[(lk1 * 4 + 2) * 68 + ln1] = p1.z;
            b0[(lk1 * 4 + 3) * 68 + ln1] = p1.w;
        }
        __syncthreads();

        for (int tile = 0; tile < 32; tile++) {
            const float* cur = hb + (tile & 1) * 2176;
            const float* wsp = ws + tile * 1024;

            if (tile < 31) {
                int k0n = (tile + 1) * 32;
                p0 = __ldcg((const float4*)&hprev[ln0 * Hh + k0n + lk0 * 4]);
                p1 = __ldcg((const float4*)&hprev[ln1 * Hh + k0n + lk1 * 4]);
            }

#pragma unroll
            for (int kk = 0; kk < 32; kk++) {
                float4 hv = *(const float4*)&cur[kk * 68 + rg * 4];
                float2 wv = *(const float2*)&wsp[kk * 32 + 2 * cp];
                acc[0][0] += hv.x * wv.x;  acc[0][1] += hv.x * wv.y;
                acc[1][0] += hv.y * wv.x;  acc[1][1] += hv.y * wv.y;
                acc[2][0] += hv.z * wv.x;  acc[2][1] += hv.z * wv.y;
                acc[3][0] += hv.w * wv.x;  acc[3][1] += hv.w * wv.y;
            }

            if (tile < 31) {
                float* nxt = hb + ((tile + 1) & 1) * 2176;
                nxt[(lk0 * 4 + 0) * 68 + ln0] = p0.x;
                nxt[(lk0 * 4 + 1) * 68 + ln0] = p0.y;
                nxt[(lk0 * 4 + 2) * 68 + ln0] = p0.z;
                nxt[(lk0 * 4 + 3) * 68 + ln0] = p0.w;
                nxt[(lk1 * 4 + 0) * 68 + ln1] = p1.x;
                nxt[(lk1 * 4 + 1) * 68 + ln1] = p1.y;
                nxt[(lk1 * 4 + 2) * 68 + ln1] = p1.z;
                nxt[(lk1 * 4 + 3) * 68 + ln1] = p1.w;
                __syncthreads();
            }
        }

        __syncthreads();
        float* sa = hb;
#pragma unroll
        for (int i = 0; i < 4; i++)
#pragma unroll
            for (int j = 0; j < 2; j++)
                sa[(rg * 4 + i) * 33 + 2 * cp + j] = acc[i][j];
        __syncthreads();

        {
            float ai = sa[en0 * 33 + ej0];
            float af = sa[en0 * 33 + 8 + ej0];
            float ao = sa[en0 * 33 + 16 + ej0];
            float ag = sa[en0 * 33 + 24 + ej0];
            float ig = 1.0f / (1.0f + expf(-ai));
            float fg = 1.0f / (1.0f + expf(-af));
            float og = 1.0f / (1.0f + expf(-ao));
            float gg = tanhf(ag);
            creg0 = fg * creg0 + ig * gg;
            float h = og * tanhf(creg0);
            int col = j0 + ej0;
            hnext[en0 * Hh + col] = h;
            out[(size_t)en0 * Tt * Hh + (size_t)t * Hh + col] = h;
        }
        {
            float ai = sa[en1 * 33 + ej1];
            float af = sa[en1 * 33 + 8 + ej1];
            float ao = sa[en1 * 33 + 16 + ej1];
            float ag = sa[en1 * 33 + 24 + ej1];
            float ig = 1.0f / (1.0f + expf(-ai));
            float fg = 1.0f / (1.0f + expf(-af));
            float og = 1.0f / (1.0f + expf(-ao));
            float gg = tanhf(ag);
            creg1 = fg * creg1 + ig * gg;
            float h = og * tanhf(creg1);
            int col = j0 + ej1;
            hnext[en1 * Hh + col] = h;
            out[(size_t)en1 * Tt * Hh + (size_t)t * Hh + col] = h;
        }

        if (t < Tt - 1) {
            __threadfence();
            __syncthreads();
            if (tid == 0) {
                atomicAdd(&g_bar, 1u);
                unsigned target = (unsigned)NCTA * (unsigned)(t + 1);
                while (*(volatile unsigned*)&g_bar < target) { }
                __threadfence();
            }
            __syncthreads();
        }
    }
}

// ---------------------------------------------------------------------------
// launch
// ---------------------------------------------------------------------------
extern "C" void kernel_launch(void* const* d_in, const int* in_sizes, int n_in,
                              void* d_out, int out_size) {
    const float* x  = (const float*)d_in[0];   // (N, T, D)
    const float* h0 = (const float*)d_in[1];   // (N, H)
    const float* Wx = (const float*)d_in[2];   // (D, 4H)
    const float* Wh = (const float*)d_in[3];   // (H, 4H)
    const float* b  = (const float*)d_in[4];   // (4H,)
    float* out = (float*)d_out;                // (N, T, H)

    static int smem_set = 0;
    const int dyn_smem_p2 = (32768 + 2 * 32 * 68) * 4;   // 148480 B
    if (!smem_set) {
        cudaFuncSetAttribute(lstm_persist,
                             cudaFuncAttributeMaxDynamicSharedMemorySize,
                             dyn_smem_p2);
        smem_set = 1;
    }

    init_kernel<<<(Nn * Hh + 255) / 256, 256>>>(h0);

    // phase-1 prep: bf16 splits
    split_x<<<(int)(((size_t)Rr * Dd / 4 + 255) / 256), 256>>>(x);
    split_w<<<(int)(((size_t)FH * Dd / 4 + 255) / 256), 256>>>(Wx);

    // phase-1 GEMM on HMMA tensor cores
    dim3 g1(FH / 128, Rr / 128);     // (32, 256)
    xw_tc<<<g1, 256>>>(b);

    // phase-2 persistent recurrence
    lstm_persist<<<NCTA, 256, dyn_smem_p2>>>(Wh, out);
}